// round 17
// baseline (speedup 1.0000x reference)
#include <cuda_runtime.h>

// CRF forward loss + argmax decode, B=64, C=2, T=65536 (H=W=256).
//
// Single kernel, 512 blocks x 2 tiles = 1024 tiles (16/batch) -> exactly ONE
// wave (5 blocks/SM cap, 740 concurrent). Per tile: cp.async-staged 32KB of
// logits in XOR-swizzled smem; each thread folds a 16-step chunk as TWO
// interleaved 8-step linear 2x2 chains (emission-difference factoring,
// 16 MUFU/thread); rescale-free linear warp/block trees (bounded growth).
// Tile1's staging is issued BEFORE tile0's compute (S0 right after reg
// loads, S1 right after decode flush) so it flies under the compute.
// Last-block ticket folds 16 mats/batch in log space + alpha0 + tree-sum.
// Decode fused via smem, coalesced scalar stores (d_out+1 is 4B-aligned).

#define NB 64
#define NT 65536
#define NTILES 1024            // 16 per batch
#define NGRID (NTILES / 2)     // 512 blocks, single wave
#define LN2F 0.6931471805599453f

typedef unsigned long long ull;

__device__ float4 g_mats[NTILES];  // per-tile 2x2 log-matrices (x=00 y=01 z=10 w=11)
__device__ int    g_sem;           // last-block ticket (winner resets)

// ---- packed f32x2 helpers ----
__device__ __forceinline__ ull packxy(float lo, float hi) {
    ull r; asm("mov.b64 %0, {%1, %2};" : "=l"(r) : "f"(lo), "f"(hi)); return r;
}
__device__ __forceinline__ ull pack2(float x) { return packxy(x, x); }
__device__ __forceinline__ void unpack2(ull a, float& lo, float& hi) {
    asm("mov.b64 {%0, %1}, %2;" : "=f"(lo), "=f"(hi) : "l"(a));
}
__device__ __forceinline__ ull mul2(ull a, ull b) {
    ull r; asm("mul.rn.f32x2 %0, %1, %2;" : "=l"(r) : "l"(a), "l"(b)); return r;
}
__device__ __forceinline__ ull fma2(ull a, ull b, ull c) {
    ull r; asm("fma.rn.f32x2 %0, %1, %2, %3;" : "=l"(r) : "l"(a), "l"(b), "l"(c)); return r;
}
__device__ __forceinline__ unsigned smem_u32(const void* p) {
    unsigned a;
    asm("{ .reg .u64 t; cvta.to.shared.u64 t, %1; cvt.u32.u64 %0, t; }" : "=r"(a) : "l"(p));
    return a;
}

struct TransP { ull T00, T10, T01, T11; };  // T'[src][dst] = exp(trans[dst*2+src])

// One linear step, exp(e0) factored out (tracked in a scalar log-sum):
//   col0' = col0*T00 + col1*T10 ;  col1' = (col0*T01 + col1*T11) * exp(e1-e0)
__device__ __forceinline__ void stepd(float d, ull& col0, ull& col1, const TransP& cs) {
    ull E = pack2(__expf(d));
    ull n0 = fma2(col0, cs.T00, mul2(col1, cs.T10));
    ull n1 = mul2(fma2(col0, cs.T01, mul2(col1, cs.T11)), E);
    col0 = n0; col1 = n1;
}

// Exact power-of-2 rescale; accumulate ex*ln2 into ls. Max entry -> [1,2).
__device__ __forceinline__ void rescale(ull& c0, ull& c1, float& ls) {
    float a, b, c, d;
    unpack2(c0, a, b);
    unpack2(c1, c, d);
    float mx = fmaxf(fmaxf(a, b), fmaxf(c, d));
    int ex = ((__float_as_int(mx) >> 23) & 0xFF) - 127;
    ull scp = pack2(__int_as_float((127 - ex) << 23));
    c0 = mul2(c0, scp);
    c1 = mul2(c1, scp);
    ls += (float)ex * LN2F;
}

// Linear 2x2 combine, self(earlier) . other(later). NO rescale (tree-safe).
__device__ __forceinline__ void combLinN(ull& c0, ull& c1, float& ls,
                                         ull o0, ull o1, float ols) {
    float q00, q10, q01, q11;
    unpack2(o0, q00, q10);
    unpack2(o1, q01, q11);
    ull r0 = fma2(c0, pack2(q00), mul2(c1, pack2(q10)));
    ull r1 = fma2(c0, pack2(q01), mul2(c1, pack2(q11)));
    c0 = r0; c1 = r1;
    ls += ols;
}

// ---- log-semiring (winner block only) ----
__device__ __forceinline__ float lse2(float x, float y) {
    float m = fmaxf(x, y);
    float d = fminf(x, y) - m;
    return m + __logf(1.f + __expf(d));
}
__device__ __forceinline__ float4 combM(float4 A, float4 Bv) {
    float4 C;
    C.x = lse2(A.x + Bv.x, A.y + Bv.z);
    C.y = lse2(A.x + Bv.y, A.y + Bv.w);
    C.z = lse2(A.z + Bv.x, A.w + Bv.z);
    C.w = lse2(A.z + Bv.y, A.w + Bv.w);
    return C;
}
__device__ __forceinline__ float4 shfl4(float4 v, int off, int w) {
    float4 r;
    r.x = __shfl_down_sync(0xffffffffu, v.x, off, w);
    r.y = __shfl_down_sync(0xffffffffu, v.y, off, w);
    r.z = __shfl_down_sync(0xffffffffu, v.z, off, w);
    r.w = __shfl_down_sync(0xffffffffu, v.w, off, w);
    return r;
}

// XOR swizzle over float4 index (permutes within each quad only).
__device__ __forceinline__ int swz(int L) {
    return (L & ~3) | ((L ^ (L >> 2) ^ (L >> 4)) & 3);
}
__device__ __forceinline__ float4 dec4(float4 A, float4 B) {
    float4 d;
    d.x = (B.x > A.x) ? 1.f : 0.f;
    d.y = (B.y > A.y) ? 1.f : 0.f;
    d.z = (B.z > A.z) ? 1.f : 0.f;
    d.w = (B.w > A.w) ? 1.f : 0.f;
    return d;
}

// ============================================================================
__global__ void __launch_bounds__(256) crf_fused(const float* __restrict__ logits,
                                                 const float* __restrict__ trans,
                                                 float* __restrict__ dec,
                                                 float* __restrict__ loss_out) {
    __shared__ float4 S0[1024];   // 16KB: state-0 emissions (swizzled)
    __shared__ float4 S1[1024];   // 16KB: state-1 emissions, then decode
    __shared__ ull    WMc0[8], WMc1[8];
    __shared__ float  WMls[8];
    __shared__ float  sll[NB];
    __shared__ int    sWin;

    int tid = threadIdx.x;

    TransP cs;
    cs.T00 = pack2(__expf(trans[0]));
    cs.T10 = pack2(__expf(trans[1]));
    cs.T01 = pack2(__expf(trans[2]));
    cs.T11 = pack2(__expf(trans[3]));

    // Stage tile 0 (both states) via cp.async.
    {
        int gt = blockIdx.x * 2;
        int b  = gt >> 4, cb = (gt & 15) * 256;
        const float4* g0 = reinterpret_cast<const float4*>(logits + ((size_t)(2 * b)    ) * NT + (size_t)cb * 16);
        const float4* g1 = reinterpret_cast<const float4*>(logits + ((size_t)(2 * b) + 1) * NT + (size_t)cb * 16);
#pragma unroll
        for (int i = 0; i < 4; ++i) {
            int L = i * 256 + tid;
            asm volatile("cp.async.cg.shared.global [%0], [%1], 16;" :: "r"(smem_u32(&S0[swz(L)])), "l"(g0 + L));
            asm volatile("cp.async.cg.shared.global [%0], [%1], 16;" :: "r"(smem_u32(&S1[swz(L)])), "l"(g1 + L));
        }
        asm volatile("cp.async.commit_group;");
    }
    asm volatile("cp.async.wait_group 0;" ::: "memory");
    __syncthreads();

#pragma unroll
    for (int t = 0; t < 2; ++t) {
        int gt = blockIdx.x * 2 + t;
        int b  = gt >> 4, cb = (gt & 15) * 256;
        float* pd = dec + (size_t)b * NT + (size_t)cb * 16;   // 4B-aligned only

        int s = (tid ^ (tid >> 2)) & 3;
        float4 A0 = S0[4 * tid + (0 ^ s)], A1 = S0[4 * tid + (1 ^ s)];
        float4 A2 = S0[4 * tid + (2 ^ s)], A3 = S0[4 * tid + (3 ^ s)];
        float4 B0 = S1[4 * tid + (0 ^ s)], B1 = S1[4 * tid + (1 ^ s)];
        float4 B2 = S1[4 * tid + (2 ^ s)], B3 = S1[4 * tid + (3 ^ s)];

        // Decode into own S1 region (regs hold B*; swz stays in own quad).
        S1[4 * tid + (0 ^ s)] = dec4(A0, B0);
        S1[4 * tid + (1 ^ s)] = dec4(A1, B1);
        S1[4 * tid + (2 ^ s)] = dec4(A2, B2);
        S1[4 * tid + (3 ^ s)] = dec4(A3, B3);

        __syncthreads();   // all S0/S1 reads done; decode visible

        // Prefetch next tile state-0 into S0 (S0 is dead now).
        if (t == 0) {
            int gn = gt + 1;
            int bn = gn >> 4, cn = (gn & 15) * 256;
            const float4* gg0 = reinterpret_cast<const float4*>(logits + ((size_t)(2 * bn)) * NT + (size_t)cn * 16);
#pragma unroll
            for (int i = 0; i < 4; ++i) {
                int L = i * 256 + tid;
                asm volatile("cp.async.cg.shared.global [%0], [%1], 16;" :: "r"(smem_u32(&S0[swz(L)])), "l"(gg0 + L));
            }
            asm volatile("cp.async.commit_group;");
        }

        // Flush decode now: frees S1 for the next tile ASAP.
        {
            const float* S1f = reinterpret_cast<const float*>(S1);
#pragma unroll
            for (int i = 0; i < 16; ++i) {
                int F = i * 256 + tid;
                pd[F] = S1f[swz(F >> 2) * 4 + (F & 3)];
            }
        }
        __syncthreads();   // all threads done reading S1

        // Issue next tile state-1 into S1; it flies under the compute below.
        if (t == 0) {
            int gn = gt + 1;
            int bn = gn >> 4, cn = (gn & 15) * 256;
            const float4* gg1 = reinterpret_cast<const float4*>(logits + ((size_t)(2 * bn) + 1) * NT + (size_t)cn * 16);
#pragma unroll
            for (int i = 0; i < 4; ++i) {
                int L = i * 256 + tid;
                asm volatile("cp.async.cg.shared.global [%0], [%1], 16;" :: "r"(smem_u32(&S1[swz(L)])), "l"(gg1 + L));
            }
            asm volatile("cp.async.commit_group;");
        }

        const bool skip0 = (gt == 0 && tid == 0);  // global t=0: alpha0 at end

        // Scalar log accumulators (off-chain FADDs) for the factored e0 sums.
        float e00 = skip0 ? 0.f : A0.x;
        float lsP = ((e00  + A0.y) + (A0.z + A0.w)) + ((A1.x + A1.y) + (A1.z + A1.w));
        float lsQ = ((A2.x + A2.y) + (A2.z + A2.w)) + ((A3.x + A3.y) + (A3.z + A3.w));

        // Chain P: steps 1..8, chain Q: steps 9..16 (independent -> 2x ILP).
        ull P0 = packxy(1.f, 0.f), P1 = packxy(0.f, 1.f);
        ull Q0 = packxy(1.f, 0.f), Q1 = packxy(0.f, 1.f);

        if (!skip0) stepd(B0.x - A0.x, P0, P1, cs);
        stepd(B2.x - A2.x, Q0, Q1, cs);
        stepd(B0.y - A0.y, P0, P1, cs);
        stepd(B2.y - A2.y, Q0, Q1, cs);
        stepd(B0.z - A0.z, P0, P1, cs);
        stepd(B2.z - A2.z, Q0, Q1, cs);
        stepd(B0.w - A0.w, P0, P1, cs);
        stepd(B2.w - A2.w, Q0, Q1, cs);
        stepd(B1.x - A1.x, P0, P1, cs);
        stepd(B3.x - A3.x, Q0, Q1, cs);
        stepd(B1.y - A1.y, P0, P1, cs);
        stepd(B3.y - A3.y, Q0, Q1, cs);
        stepd(B1.z - A1.z, P0, P1, cs);
        stepd(B3.z - A3.z, Q0, Q1, cs);
        stepd(B1.w - A1.w, P0, P1, cs);
        stepd(B3.w - A3.w, Q0, Q1, cs);

        // Normalize chains; combine P(earlier).Q(later); normalize result.
        rescale(P0, P1, lsP);
        rescale(Q0, Q1, lsQ);
        combLinN(P0, P1, lsP, Q0, Q1, lsQ);
        rescale(P0, P1, lsP);   // tree inputs: max in [1,2)

        // Ordered warp tree, LINEAR, no per-level rescale (5 levels <= 2^63).
#pragma unroll
        for (int off = 1; off < 32; off <<= 1) {
            ull  o0  = __shfl_down_sync(0xffffffffu, P0, off, 32);
            ull  o1  = __shfl_down_sync(0xffffffffu, P1, off, 32);
            float ol = __shfl_down_sync(0xffffffffu, lsP, off, 32);
            combLinN(P0, P1, lsP, o0, o1, ol);
        }
        if ((tid & 31) == 0) {
            rescale(P0, P1, lsP);      // normalize for the block tree
            WMc0[tid >> 5] = P0;
            WMc1[tid >> 5] = P1;
            WMls[tid >> 5] = lsP;
        }
        __syncthreads();

        // Block tree: warp 0 folds 8 warp-mats; 3 levels no-rescale (<= 2^15).
        if (tid < 32) {
            ull  c0 = WMc0[tid & 7];
            ull  c1 = WMc1[tid & 7];
            float ls = WMls[tid & 7];
#pragma unroll
            for (int off = 1; off < 8; off <<= 1) {
                ull  o0  = __shfl_down_sync(0xffffffffu, c0, off, 8);
                ull  o1  = __shfl_down_sync(0xffffffffu, c1, off, 8);
                float ol = __shfl_down_sync(0xffffffffu, ls, off, 8);
                combLinN(c0, c1, ls, o0, o1, ol);
            }
            if (tid == 0) {
                float m00, m10, m01, m11;
                unpack2(c0, m00, m10);
                unpack2(c1, m01, m11);
                float4 m;
                m.x = __logf(m00) + ls;
                m.y = __logf(m01) + ls;
                m.z = __logf(m10) + ls;
                m.w = __logf(m11) + ls;
                g_mats[gt] = m;
            }
        }

        if (t == 0) {
            asm volatile("cp.async.wait_group 0;" ::: "memory");
            __syncthreads();   // next tile's S0/S1 ready; WM consumed
        }
    }

    if (tid == 0) {
        __threadfence();
        int tk = atomicAdd(&g_sem, 1);
        sWin = (tk == NGRID - 1);
    }
    __syncthreads();
    if (!sWin) return;

    // ======== winner block: final combine (log space, time-ordered) ========
    {
        int bb2 = tid >> 2;           // batch (4 threads per batch)
        int q   = tid & 3;
        const float4* base = g_mats + bb2 * 16 + q * 4;
        float4 v0 = base[0], v1 = base[1], v2 = base[2], v3 = base[3];
        float4 mm = combM(combM(v0, v1), combM(v2, v3));
        mm = combM(mm, shfl4(mm, 1, 4));
        mm = combM(mm, shfl4(mm, 2, 4));
        if (q == 0) {
            float a0 = logits[(size_t)(2 * bb2)     * NT];  // alpha0[0]
            float a1 = logits[(size_t)(2 * bb2 + 1) * NT];  // alpha0[1]
            float w0 = lse2(a0 + mm.x, a1 + mm.z);
            float w1 = lse2(a0 + mm.y, a1 + mm.w);
            sll[bb2] = lse2(w0, w1);
        }
    }
    __syncthreads();
    if (tid < 32) {
        float v = sll[tid] + sll[tid + 32];
#pragma unroll
        for (int off = 16; off >= 1; off >>= 1)
            v += __shfl_down_sync(0xffffffffu, v, off, 32);
        if (tid == 0) {
            if (loss_out != nullptr) loss_out[0] = -v / (float)NB;
            g_sem = 0;   // reset for next graph replay
        }
    }
}

extern "C" void kernel_launch(void* const* d_in, const int* in_sizes, int n_in,
                              void* d_out, int out_size) {
    const float* logits = (const float*)d_in[0];
    // d_in[1] = mask (all-ones; unused by the reference math)
    const float* trans  = (const float*)d_in[2];
    float* out = (float*)d_out;

    int base = out_size - NB * NT;   // expected 1 (loss scalar before decoded)
    if (base < 0) base = 0;

    crf_fused<<<NGRID, 256>>>(logits, trans, out + base, base > 0 ? out : nullptr);
}